// round 7
// baseline (speedup 1.0000x reference)
#include <cuda_runtime.h>
#include <cuda_fp16.h>
#include <math.h>

#define Hd 1024
#define Dm 512
#define Vn 50257
#define Sn 128
#define An 1024
#define Tn 25
#define SOS 1
#define NB ((Vn + 7) / 8)       /* 6283 blocks, 8 rows each */
#define NWORK 128               /* worker blocks (wave-1 co-resident) */

// ---------------- persistent device scratch ----------------
__device__ float g_hbuf[2][Hd];
__device__ float g_attn[An];
__device__ float g_scores[Sn];
__device__ float g_M[Sn][Hd];             // emb @ Wq, precomputed per launch
__device__ unsigned long long g_apk[2];   // packed argmax, per parity
__device__ float g_sum[2];                // sum exp(logit), per parity
__device__ __half g_Wh[(size_t)Vn * 2048];    // fp16 Wout (206 MB)
__device__ __half g_Wih_h[3 * Hd * Dm];       // fp16 Wih
__device__ __half g_Whh_h[3 * Hd * Hd];       // fp16 Whh
__device__ unsigned g_cnt = 0;
__device__ volatile unsigned g_gen = 0;
__device__ volatile int g_ready = -1;     // step-tagged ready flag

__device__ __forceinline__ float warp_sum(float v) {
#pragma unroll
    for (int o = 16; o > 0; o >>= 1) v += __shfl_down_sync(0xffffffffu, v, o);
    return v;
}
__device__ __forceinline__ unsigned long long umaxll(unsigned long long a, unsigned long long b) {
    return a > b ? a : b;
}

// grid barrier among the NWORK worker blocks (all wave-1 resident)
__device__ __forceinline__ void gsync() {
    __syncthreads();
    if (threadIdx.x == 0) {
        __threadfence();
        unsigned gen = g_gen;
        if (atomicAdd(&g_cnt, 1u) == NWORK - 1) {
            g_cnt = 0;
            __threadfence();
            g_gen = gen + 1;
        } else {
            while (g_gen == gen) { __nanosleep(64); }
        }
        __threadfence();
    }
    __syncthreads();
}

// ------------- K0: fp32 -> fp16 conversions (once per launch) -------------
__device__ void cvt8(const float* __restrict__ src, __half* __restrict__ dst, size_t n8,
                     size_t base, size_t stride)
{
    for (size_t i = base; i < n8; i += stride) {
        const float4* s4 = (const float4*)src + 2 * i;
        float4 a = s4[0], b = s4[1];
        uint4 u;
        ((__half2*)&u)[0] = __floats2half2_rn(a.x, a.y);
        ((__half2*)&u)[1] = __floats2half2_rn(a.z, a.w);
        ((__half2*)&u)[2] = __floats2half2_rn(b.x, b.y);
        ((__half2*)&u)[3] = __floats2half2_rn(b.z, b.w);
        ((uint4*)dst)[i] = u;
    }
}

__global__ void k_convert(const float* __restrict__ Wout, const float* __restrict__ Wih,
                          const float* __restrict__ Whh)
{
    size_t base = (size_t)blockIdx.x * blockDim.x + threadIdx.x;
    size_t stride = (size_t)gridDim.x * blockDim.x;
    cvt8(Wout, g_Wh, (size_t)Vn * 2048 / 8, base, stride);
    cvt8(Wih, g_Wih_h, (size_t)3 * Hd * Dm / 8, base, stride);
    cvt8(Whh, g_Whh_h, (size_t)3 * Hd * Hd / 8, base, stride);
}

// ------------- K0b: M = emb @ Wq (once per launch) -------------
__global__ void k_prep(const float* __restrict__ emb, const float* __restrict__ Wq)
{
    __shared__ float scol[8][Hd];
    const int hbase = blockIdx.x * 8;
    for (int idx = threadIdx.x; idx < 8 * Hd; idx += 128) {
        int c = idx & 7, a = idx >> 3;
        scol[c][a] = Wq[(size_t)a * Hd + hbase + c];
    }
    __syncthreads();
    const int s = threadIdx.x;
    float acc[8] = {0.f, 0.f, 0.f, 0.f, 0.f, 0.f, 0.f, 0.f};
    const float4* e4 = (const float4*)(emb + (size_t)s * An);
    for (int a4 = 0; a4 < An / 4; a4++) {
        float4 e = e4[a4];
#pragma unroll
        for (int c = 0; c < 8; c++)
            acc[c] += e.x * scol[c][4 * a4] + e.y * scol[c][4 * a4 + 1]
                    + e.z * scol[c][4 * a4 + 2] + e.w * scol[c][4 * a4 + 3];
    }
#pragma unroll
    for (int c = 0; c < 8; c++) g_M[s][hbase + c] = acc[c];
}

// ---------------- K1: one kernel per step ----------------
// blocks 0..NWORK-1: finalize + GRU + scores + attn, then publish ready
// all blocks: prev-step logZ subtract for own rows, then logits GEMV + atomics
__global__ void __launch_bounds__(256, 4)
k_step(const float* __restrict__ hidden, const float* __restrict__ emb,
       const float* __restrict__ E, const float* __restrict__ bih,
       const float* __restrict__ bhh, const float* __restrict__ bout,
       float* __restrict__ out, int step)
{
    const int tid = threadIdx.x, bid = blockIdx.x;
    const int wid = tid >> 5, lane = tid & 31;

    // ---- prev-step finalize (every block, independent of ready flag) ----
    int word = SOS;
    if (step > 0) {
        unsigned long long best = g_apk[(step - 1) & 1];
        word = (int)(0xFFFFFFFFu - (unsigned)(best & 0xFFFFFFFFull));
        float logZ = logf(g_sum[(step - 1) & 1]);
        if (bid == 0 && tid == 0)
            out[(size_t)Tn * Vn + (size_t)Tn * Sn + (step - 1)] = (float)word;
        if (tid < 8) {
            int pv = bid * 8 + tid;
            if (pv < Vn) out[(size_t)(step - 1) * Vn + pv] -= logZ;
        }
        if (step == Tn) return;    // tail launch: finalize only
    }

    const float* h = (step == 0) ? hidden : g_hbuf[(step - 1) & 1];
    float* hn = g_hbuf[step & 1];

    if (bid < NWORK) {
        // reset this step's atomic slot BEFORE the first gsync
        if (bid == 0 && tid == 0) { g_apk[step & 1] = 0ull; g_sum[step & 1] = 0.f; }

        // ===== Phase A: GRU — warp per unit, loop 3 gates (fp16 weights) =====
        {
            const int u = bid * 8 + wid;
            const float4* x4 = (const float4*)(E + (size_t)word * Dm);
            const float4* h4 = (const float4*)h;
            float gi[3], gh[3];
#pragma unroll
            for (int g = 0; g < 3; g++) {
                const int row = g * Hd + u;
                const uint4* wi = (const uint4*)(g_Wih_h + (size_t)row * Dm);
                const uint4* wh = (const uint4*)(g_Whh_h + (size_t)row * Hd);
                float si = 0.f, sh = 0.f;
#pragma unroll
                for (int j = 0; j < 2; j++) {
                    uint4 u8 = wi[lane + 32 * j];
                    float4 xa = x4[2 * (lane + 32 * j)];
                    float4 xb = x4[2 * (lane + 32 * j) + 1];
                    const __half2* hp = (const __half2*)&u8;
                    float2 w0 = __half22float2(hp[0]);
                    float2 w1 = __half22float2(hp[1]);
                    float2 w2 = __half22float2(hp[2]);
                    float2 w3 = __half22float2(hp[3]);
                    si += w0.x*xa.x + w0.y*xa.y + w1.x*xa.z + w1.y*xa.w
                        + w2.x*xb.x + w2.y*xb.y + w3.x*xb.z + w3.y*xb.w;
                }
#pragma unroll
                for (int j = 0; j < 4; j++) {
                    uint4 u8 = wh[lane + 32 * j];
                    float4 ha = h4[2 * (lane + 32 * j)];
                    float4 hb = h4[2 * (lane + 32 * j) + 1];
                    const __half2* hp = (const __half2*)&u8;
                    float2 w0 = __half22float2(hp[0]);
                    float2 w1 = __half22float2(hp[1]);
                    float2 w2 = __half22float2(hp[2]);
                    float2 w3 = __half22float2(hp[3]);
                    sh += w0.x*ha.x + w0.y*ha.y + w1.x*ha.z + w1.y*ha.w
                        + w2.x*hb.x + w2.y*hb.y + w3.x*hb.z + w3.y*hb.w;
                }
                si = warp_sum(si); sh = warp_sum(sh);
                gi[g] = si; gh[g] = sh;
            }
            if (lane == 0) {
                float r = 1.f / (1.f + __expf(-(gi[0] + bih[u]          + gh[0] + bhh[u])));
                float z = 1.f / (1.f + __expf(-(gi[1] + bih[Hd + u]     + gh[1] + bhh[Hd + u])));
                float n = tanhf(gi[2] + bih[2 * Hd + u] + r * (gh[2] + bhh[2 * Hd + u]));
                hn[u] = (1.f - z) * n + z * h[u];
            }
        }
        gsync();

        // ===== Phase C: scores[bid] = M[bid] . hn (256 threads x float4) =====
        {
            __shared__ float scred[8];
            float4 m4 = ((const float4*)g_M[bid])[tid];
            float4 h4v = ((const float4*)hn)[tid];
            float s = m4.x*h4v.x + m4.y*h4v.y + m4.z*h4v.z + m4.w*h4v.w;
            s = warp_sum(s);
            if (lane == 0) scred[wid] = s;
            __syncthreads();
            if (tid == 0) {
                float t2 = 0.f;
#pragma unroll
                for (int i = 0; i < 8; i++) t2 += scred[i];
                g_scores[bid] = t2;
            }
        }
        gsync();

        // ===== Phase D: softmax (per-warp redundant) + attn — warp per dim =====
        {
            const int d = bid + NWORK * wid;   // 0..1023
            float sc0 = g_scores[lane];
            float sc1 = g_scores[lane + 32];
            float sc2 = g_scores[lane + 64];
            float sc3 = g_scores[lane + 96];
            float mx = fmaxf(fmaxf(sc0, sc1), fmaxf(sc2, sc3));
#pragma unroll
            for (int o = 16; o > 0; o >>= 1)
                mx = fmaxf(mx, __shfl_xor_sync(0xffffffffu, mx, o));
            float e0 = __expf(sc0 - mx), e1 = __expf(sc1 - mx);
            float e2 = __expf(sc2 - mx), e3 = __expf(sc3 - mx);
            float ssum = e0 + e1 + e2 + e3;
#pragma unroll
            for (int o = 16; o > 0; o >>= 1)
                ssum += __shfl_xor_sync(0xffffffffu, ssum, o);
            float inv = 1.f / ssum;
            float part = e0 * inv * emb[(size_t)lane * An + d]
                       + e1 * inv * emb[(size_t)(lane + 32) * An + d]
                       + e2 * inv * emb[(size_t)(lane + 64) * An + d]
                       + e3 * inv * emb[(size_t)(lane + 96) * An + d];
            part = warp_sum(part);
            if (lane == 0) g_attn[d] = part;
            if (d == 0) {
                float* wo = out + (size_t)Tn * Vn + (size_t)step * Sn;
                wo[lane]      = e0 * inv;
                wo[lane + 32] = e1 * inv;
                wo[lane + 64] = e2 * inv;
                wo[lane + 96] = e3 * inv;
            }
        }
        gsync();
        if (bid == 0 && tid == 0) {
            __threadfence();
            g_ready = step;          // publish: hn + g_attn complete
        }
    } else {
        // waiter: spin until this step's activations are published
        if (tid == 0) {
            while (g_ready != step) { __nanosleep(128); }
        }
        __syncthreads();
        __threadfence();
    }

    // ================= logits GEMV (all blocks) =================
    __shared__ __align__(16) float merge[2 * Hd];
    __shared__ unsigned long long spk[8];
    __shared__ float sse[8];
    for (int i = tid; i < Hd; i += 256) { merge[i] = hn[i]; merge[Hd + i] = g_attn[i]; }
    __syncthreads();

    int v = bid * 8 + wid;
    float logit = __int_as_float(0xff800000);
    bool valid = (v < Vn);
    if (valid) {
        const uint4* w4 = (const uint4*)(g_Wh + (size_t)v * (2 * Hd));
        const float4* m4 = (const float4*)merge;
        float s = 0.f;
#pragma unroll
        for (int j = 0; j < 8; j++) {
            uint4 u = w4[lane + 32 * j];
            float4 ma = m4[2 * (lane + 32 * j)];
            float4 mb = m4[2 * (lane + 32 * j) + 1];
            const __half2* hp = (const __half2*)&u;
            float2 f0 = __half22float2(hp[0]);
            float2 f1 = __half22float2(hp[1]);
            float2 f2 = __half22float2(hp[2]);
            float2 f3 = __half22float2(hp[3]);
            s += f0.x*ma.x + f0.y*ma.y + f1.x*ma.z + f1.y*ma.w
               + f2.x*mb.x + f2.y*mb.y + f3.x*mb.z + f3.y*mb.w;
        }
        s = warp_sum(s);
        if (lane == 0) {
            logit = s + bout[v];
            out[(size_t)step * Vn + v] = logit;   // raw; logZ subtracted next step
        }
    }
    if (lane == 0) {
        unsigned long long pk = 0ull;
        float e = 0.f;
        if (valid) {
            unsigned b = __float_as_uint(logit);
            unsigned key = (b & 0x80000000u) ? ~b : (b | 0x80000000u);
            pk = ((unsigned long long)key << 32) |
                 (unsigned long long)(0xFFFFFFFFu - (unsigned)v);
            e = __expf(logit);
        }
        spk[wid] = pk; sse[wid] = e;
    }
    __syncthreads();
    if (tid == 0) {
        unsigned long long best = spk[0];
        float tot = sse[0];
#pragma unroll
        for (int i = 1; i < 8; i++) { best = umaxll(best, spk[i]); tot += sse[i]; }
        atomicMax(&g_apk[step & 1], best);
        atomicAdd(&g_sum[step & 1], tot);
    }
}

// ---------------- launcher: 2 + 26 graph nodes ----------------
extern "C" void kernel_launch(void* const* d_in, const int* in_sizes, int n_in,
                              void* d_out, int out_size)
{
    const float* hidden = (const float*)d_in[0];
    const float* emb    = (const float*)d_in[1];
    const float* E      = (const float*)d_in[2];
    const float* Wih    = (const float*)d_in[3];
    const float* Whh    = (const float*)d_in[4];
    const float* bih    = (const float*)d_in[5];
    const float* bhh    = (const float*)d_in[6];
    const float* Wq     = (const float*)d_in[7];
    const float* Wout   = (const float*)d_in[8];
    const float* bout   = (const float*)d_in[9];
    float* out = (float*)d_out;

    k_convert<<<2048, 256>>>(Wout, Wih, Whh);
    k_prep<<<Sn, 128>>>(emb, Wq);
    for (int t = 0; t < Tn; t++)
        k_step<<<NB, 256>>>(hidden, emb, E, bih, bhh, bout, out, t);
    k_step<<<NB, 256>>>(hidden, emb, E, bih, bhh, bout, out, Tn);  // tail finalize
}

// round 8
// speedup vs baseline: 1.4425x; 1.4425x over previous
#include <cuda_runtime.h>
#include <cuda_fp16.h>
#include <math.h>

#define Hd 1024
#define Dm 512
#define Vn 50257
#define Sn 128
#define An 1024
#define Tn 25
#define SOS 1
#define NB3 ((Vn + 7) / 8)      /* 6283 logits blocks, 8 rows each */
#define NBS 128                 /* small-kernel blocks (co-resident) */
#define NTS 768                 /* small-kernel threads (24 warps) */

// ---------------- persistent device scratch ----------------
__device__ float g_hbuf[2][Hd];
__device__ float g_attn[An];
__device__ float g_scores[Sn];
__device__ float g_M[Sn][Hd];             // emb @ Wq, precomputed per launch
__device__ float g_logZ;
__device__ unsigned long long g_apk[2];   // packed argmax, per parity
__device__ float g_sum[2];                // sum exp(logit), per parity
__device__ __half g_Wh[(size_t)Vn * 2048];    // fp16 Wout (206 MB)
__device__ __half g_Wih_h[3 * Hd * Dm];       // fp16 Wih
__device__ __half g_Whh_h[3 * Hd * Hd];       // fp16 Whh
__device__ unsigned g_cnt = 0;
__device__ volatile unsigned g_gen = 0;

__device__ __forceinline__ float warp_sum(float v) {
#pragma unroll
    for (int o = 16; o > 0; o >>= 1) v += __shfl_down_sync(0xffffffffu, v, o);
    return v;
}
__device__ __forceinline__ unsigned long long umaxll(unsigned long long a, unsigned long long b) {
    return a > b ? a : b;
}

// grid barrier: NBS blocks co-resident
__device__ __forceinline__ void gsync() {
    __syncthreads();
    if (threadIdx.x == 0) {
        __threadfence();
        unsigned gen = g_gen;
        if (atomicAdd(&g_cnt, 1u) == NBS - 1) {
            g_cnt = 0;
            __threadfence();
            g_gen = gen + 1;
        } else {
            while (g_gen == gen) { __nanosleep(64); }
        }
        __threadfence();
    }
    __syncthreads();
}

// ------------- K0: fp32 -> fp16 conversions (once per launch) -------------
__device__ void cvt8(const float* __restrict__ src, __half* __restrict__ dst, size_t n8,
                     size_t base, size_t stride)
{
    for (size_t i = base; i < n8; i += stride) {
        const float4* s4 = (const float4*)src + 2 * i;
        float4 a = s4[0], b = s4[1];
        uint4 u;
        ((__half2*)&u)[0] = __floats2half2_rn(a.x, a.y);
        ((__half2*)&u)[1] = __floats2half2_rn(a.z, a.w);
        ((__half2*)&u)[2] = __floats2half2_rn(b.x, b.y);
        ((__half2*)&u)[3] = __floats2half2_rn(b.z, b.w);
        ((uint4*)dst)[i] = u;
    }
}

__global__ void k_convert(const float* __restrict__ Wout, const float* __restrict__ Wih,
                          const float* __restrict__ Whh)
{
    size_t base = (size_t)blockIdx.x * blockDim.x + threadIdx.x;
    size_t stride = (size_t)gridDim.x * blockDim.x;
    cvt8(Wout, g_Wh, (size_t)Vn * 2048 / 8, base, stride);
    cvt8(Wih, g_Wih_h, (size_t)3 * Hd * Dm / 8, base, stride);
    cvt8(Whh, g_Whh_h, (size_t)3 * Hd * Hd / 8, base, stride);
}

// ------------- K0b: M = emb @ Wq (once per launch) -------------
__global__ void k_prep(const float* __restrict__ emb, const float* __restrict__ Wq)
{
    __shared__ float scol[8][Hd];
    const int hbase = blockIdx.x * 8;
    for (int idx = threadIdx.x; idx < 8 * Hd; idx += 128) {
        int c = idx & 7, a = idx >> 3;
        scol[c][a] = Wq[(size_t)a * Hd + hbase + c];
    }
    __syncthreads();
    const int s = threadIdx.x;
    float acc[8] = {0.f, 0.f, 0.f, 0.f, 0.f, 0.f, 0.f, 0.f};
    const float4* e4 = (const float4*)(emb + (size_t)s * An);
    for (int a4 = 0; a4 < An / 4; a4++) {
        float4 e = e4[a4];
#pragma unroll
        for (int c = 0; c < 8; c++)
            acc[c] += e.x * scol[c][4 * a4] + e.y * scol[c][4 * a4 + 1]
                    + e.z * scol[c][4 * a4 + 2] + e.w * scol[c][4 * a4 + 3];
    }
#pragma unroll
    for (int c = 0; c < 8; c++) g_M[s][hbase + c] = acc[c];
}

// ---- K1: fused small kernel: scalar finalize + GRU + scores + attn ----
__global__ void __launch_bounds__(NTS, 1)
k_small(const float* __restrict__ hidden, const float* __restrict__ emb,
        const float* __restrict__ E, const float* __restrict__ bih,
        const float* __restrict__ bhh, float* __restrict__ out, int step)
{
    const int tid = threadIdx.x, bid = blockIdx.x;
    const int wid = tid >> 5, lane = tid & 31;

    __shared__ float sgi[8][3], sgh[8][3];
    __shared__ float scred[16];

    int word = SOS;
    if (step > 0) {
        unsigned long long best = g_apk[(step - 1) & 1];
        word = (int)(0xFFFFFFFFu - (unsigned)(best & 0xFFFFFFFFull));
        float logZ = logf(g_sum[(step - 1) & 1]);
        if (bid == 0 && tid == 0) {
            g_logZ = logZ;
            out[(size_t)Tn * Vn + (size_t)Tn * Sn + (step - 1)] = (float)word;
        }
        if (step == Tn) {   // tail: finalize last step's log_softmax
            for (int v = bid * NTS + tid; v < Vn; v += NBS * NTS)
                out[(size_t)(step - 1) * Vn + v] -= logZ;
            return;
        }
    }
    if (bid == 0 && tid == 0) { g_apk[step & 1] = 0ull; g_sum[step & 1] = 0.f; }

    const float* h = (step == 0) ? hidden : g_hbuf[(step - 1) & 1];
    float* hn = g_hbuf[step & 1];

    // ===== Phase A: GRU — warp per (unit, gate), fp16 weights ====
    {
        const int ul = wid / 3;        // local unit 0..7
        const int g  = wid % 3;        // gate 0=r 1=z 2=n
        const int u  = bid * 8 + ul;
        const int row = g * Hd + u;
        const float4* x4 = (const float4*)(E + (size_t)word * Dm);
        const float4* h4 = (const float4*)h;
        const uint4* wi = (const uint4*)(g_Wih_h + (size_t)row * Dm);
        const uint4* wh = (const uint4*)(g_Whh_h + (size_t)row * Hd);
        float si = 0.f, sh = 0.f;
#pragma unroll
        for (int j = 0; j < 2; j++) {
            uint4 u8 = wi[lane + 32 * j];
            float4 xa = x4[2 * (lane + 32 * j)];
            float4 xb = x4[2 * (lane + 32 * j) + 1];
            const __half2* hp = (const __half2*)&u8;
            float2 w0 = __half22float2(hp[0]);
            float2 w1 = __half22float2(hp[1]);
            float2 w2 = __half22float2(hp[2]);
            float2 w3 = __half22float2(hp[3]);
            si += w0.x*xa.x + w0.y*xa.y + w1.x*xa.z + w1.y*xa.w
                + w2.x*xb.x + w2.y*xb.y + w3.x*xb.z + w3.y*xb.w;
        }
#pragma unroll
        for (int j = 0; j < 4; j++) {
            uint4 u8 = wh[lane + 32 * j];
            float4 ha = h4[2 * (lane + 32 * j)];
            float4 hb = h4[2 * (lane + 32 * j) + 1];
            const __half2* hp = (const __half2*)&u8;
            float2 w0 = __half22float2(hp[0]);
            float2 w1 = __half22float2(hp[1]);
            float2 w2 = __half22float2(hp[2]);
            float2 w3 = __half22float2(hp[3]);
            sh += w0.x*ha.x + w0.y*ha.y + w1.x*ha.z + w1.y*ha.w
                + w2.x*hb.x + w2.y*hb.y + w3.x*hb.z + w3.y*hb.w;
        }
        si = warp_sum(si); sh = warp_sum(sh);
        if (lane == 0) { sgi[ul][g] = si + bih[row]; sgh[ul][g] = sh + bhh[row]; }
        __syncthreads();
        if (tid < 8) {
            int u2 = bid * 8 + tid;
            float r = 1.f / (1.f + __expf(-(sgi[tid][0] + sgh[tid][0])));
            float z = 1.f / (1.f + __expf(-(sgi[tid][1] + sgh[tid][1])));
            float n = tanhf(sgi[tid][2] + r * sgh[tid][2]);
            hn[u2] = (1.f - z) * n + z * h[u2];
        }
    }
    gsync();

    // ===== Phase C: scores[bid] = M[bid] . hn (512 threads) =====
    if (tid < 512) {
        float2 m2 = ((const float2*)g_M[bid])[tid];
        float2 h2 = ((const float2*)hn)[tid];
        float s = m2.x * h2.x + m2.y * h2.y;
        s = warp_sum(s);
        if (lane == 0) scred[wid] = s;
    }
    __syncthreads();
    if (tid == 0) {
        float s = 0.f;
#pragma unroll
        for (int i = 0; i < 16; i++) s += scred[i];
        g_scores[bid] = s;
    }
    gsync();

    // ===== Phase D: softmax (per-warp redundant) + attn — warp per dim =====
    if (wid < 8) {
        const int d = bid + NBS * wid;   // 0..1023
        float sc0 = g_scores[lane];
        float sc1 = g_scores[lane + 32];
        float sc2 = g_scores[lane + 64];
        float sc3 = g_scores[lane + 96];
        float mx = fmaxf(fmaxf(sc0, sc1), fmaxf(sc2, sc3));
#pragma unroll
        for (int o = 16; o > 0; o >>= 1)
            mx = fmaxf(mx, __shfl_xor_sync(0xffffffffu, mx, o));
        float e0 = __expf(sc0 - mx), e1 = __expf(sc1 - mx);
        float e2 = __expf(sc2 - mx), e3 = __expf(sc3 - mx);
        float ssum = e0 + e1 + e2 + e3;
#pragma unroll
        for (int o = 16; o > 0; o >>= 1)
            ssum += __shfl_xor_sync(0xffffffffu, ssum, o);
        float inv = 1.f / ssum;
        float part = e0 * inv * emb[(size_t)lane * An + d]
                   + e1 * inv * emb[(size_t)(lane + 32) * An + d]
                   + e2 * inv * emb[(size_t)(lane + 64) * An + d]
                   + e3 * inv * emb[(size_t)(lane + 96) * An + d];
        part = warp_sum(part);
        if (lane == 0) g_attn[d] = part;
        if (d == 0) {
            float* wo = out + (size_t)Tn * Vn + (size_t)step * Sn;
            wo[lane]      = e0 * inv;
            wo[lane + 32] = e1 * inv;
            wo[lane + 64] = e2 * inv;
            wo[lane + 96] = e3 * inv;
        }
    }
}

// ------- K2: logits GEMV (fp16, 8 rows/block, 256 thr) + atomic finalize -------
__global__ void __launch_bounds__(256)
k_logits(const float* __restrict__ bout, float* __restrict__ out, int step)
{
    __shared__ __align__(16) float merge[2 * Hd];
    __shared__ unsigned long long spk[8];
    __shared__ float sse[8];
    const int tid = threadIdx.x, wid = tid >> 5, lane = tid & 31;
    const float* hn = g_hbuf[step & 1];

    if (step > 0 && tid < 8) {
        int pv = blockIdx.x * 8 + tid;
        if (pv < Vn) out[(size_t)(step - 1) * Vn + pv] -= g_logZ;
    }
    for (int i = tid; i < Hd; i += 256) { merge[i] = hn[i]; merge[Hd + i] = g_attn[i]; }
    __syncthreads();

    int v = blockIdx.x * 8 + wid;
    float logit = __int_as_float(0xff800000);
    bool valid = (v < Vn);
    if (valid) {
        const uint4* w4 = (const uint4*)(g_Wh + (size_t)v * (2 * Hd));
        const float4* m4 = (const float4*)merge;
        float s = 0.f;
#pragma unroll
        for (int j = 0; j < 8; j++) {
            uint4 u = w4[lane + 32 * j];
            float4 ma = m4[2 * (lane + 32 * j)];
            float4 mb = m4[2 * (lane + 32 * j) + 1];
            const __half2* hp = (const __half2*)&u;
            float2 f0 = __half22float2(hp[0]);
            float2 f1 = __half22float2(hp[1]);
            float2 f2 = __half22float2(hp[2]);
            float2 f3 = __half22float2(hp[3]);
            s += f0.x*ma.x + f0.y*ma.y + f1.x*ma.z + f1.y*ma.w
               + f2.x*mb.x + f2.y*mb.y + f3.x*mb.z + f3.y*mb.w;
        }
        s = warp_sum(s);
        if (lane == 0) {
            logit = s + bout[v];
            out[(size_t)step * Vn + v] = logit;   // raw; subtracted next step
        }
    }
    if (lane == 0) {
        unsigned long long pk = 0ull;
        float e = 0.f;
        if (valid) {
            unsigned b = __float_as_uint(logit);
            unsigned key = (b & 0x80000000u) ? ~b : (b | 0x80000000u);
            pk = ((unsigned long long)key << 32) |
                 (unsigned long long)(0xFFFFFFFFu - (unsigned)v);
            e = __expf(logit);
        }
        spk[wid] = pk; sse[wid] = e;
    }
    __syncthreads();
    if (tid == 0) {
        unsigned long long best = spk[0];
        float tot = sse[0];
#pragma unroll
        for (int i = 1; i < 8; i++) { best = umaxll(best, spk[i]); tot += sse[i]; }
        atomicMax(&g_apk[step & 1], best);
        atomicAdd(&g_sum[step & 1], tot);
    }
}

// ---------------- launcher ----------------
extern "C" void kernel_launch(void* const* d_in, const int* in_sizes, int n_in,
                              void* d_out, int out_size)
{
    const float* hidden = (const float*)d_in[0];
    const float* emb    = (const float*)d_in[1];
    const float* E      = (const float*)d_in[2];
    const float* Wih    = (const float*)d_in[3];
    const float* Whh    = (const float*)d_in[4];
    const float* bih    = (const float*)d_in[5];
    const float* bhh    = (const float*)d_in[6];
    const float* Wq     = (const float*)d_in[7];
    const float* Wout   = (const float*)d_in[8];
    const float* bout   = (const float*)d_in[9];
    float* out = (float*)d_out;

    k_convert<<<2048, 256>>>(Wout, Wih, Whh);
    k_prep<<<Sn, 128>>>(emb, Wq);
    for (int t = 0; t < Tn; t++) {
        k_small <<<NBS, NTS>>>(hidden, emb, E, bih, bhh, out, t);
        k_logits<<<NB3, 256>>>(bout, out, t);
    }
    k_small<<<NBS, NTS>>>(hidden, emb, E, bih, bhh, out, Tn);
}

// round 9
// speedup vs baseline: 1.5671x; 1.0864x over previous
#include <cuda_runtime.h>
#include <cuda_fp16.h>
#include <math.h>

#define Hd 1024
#define Dm 512
#define Vn 50257
#define Sn 128
#define An 1024
#define Tn 25
#define SOS 1
#define RPB 16                       /* logits rows per block (2 per warp) */
#define NB3 ((Vn + RPB - 1) / RPB)   /* 3142 logits blocks */
#define NBS 128                      /* small-kernel blocks (co-resident) */
#define NTS 768                      /* small-kernel threads (24 warps) */

// ---------------- persistent device scratch ----------------
__device__ float g_hbuf[2][Hd];
__device__ float g_attn[An];
__device__ float g_scores[Sn];
__device__ float g_M[Sn][Hd];             // emb @ Wq, precomputed per launch
__device__ float g_logZ;
__device__ unsigned long long g_apk[2];   // packed argmax, per parity
__device__ float g_sum[2];                // sum exp(logit), per parity
__device__ __half g_Wh[(size_t)Vn * 2048];    // fp16 Wout (206 MB)
__device__ __half g_Wih_h[3 * Hd * Dm];       // fp16 Wih
__device__ __half g_Whh_h[3 * Hd * Hd];       // fp16 Whh
__device__ unsigned g_cnt = 0;
__device__ volatile unsigned g_gen = 0;

__device__ __forceinline__ float warp_sum(float v) {
#pragma unroll
    for (int o = 16; o > 0; o >>= 1) v += __shfl_down_sync(0xffffffffu, v, o);
    return v;
}
__device__ __forceinline__ unsigned long long umaxll(unsigned long long a, unsigned long long b) {
    return a > b ? a : b;
}

// grid barrier: NBS blocks co-resident
__device__ __forceinline__ void gsync() {
    __syncthreads();
    if (threadIdx.x == 0) {
        __threadfence();
        unsigned gen = g_gen;
        if (atomicAdd(&g_cnt, 1u) == NBS - 1) {
            g_cnt = 0;
            __threadfence();
            g_gen = gen + 1;
        } else {
            while (g_gen == gen) { __nanosleep(64); }
        }
        __threadfence();
    }
    __syncthreads();
}

// ------------- K0: fp32 -> fp16 conversions (once per launch) -------------
__device__ void cvt8(const float* __restrict__ src, __half* __restrict__ dst, size_t n8,
                     size_t base, size_t stride)
{
    for (size_t i = base; i < n8; i += stride) {
        const float4* s4 = (const float4*)src + 2 * i;
        float4 a = s4[0], b = s4[1];
        uint4 u;
        ((__half2*)&u)[0] = __floats2half2_rn(a.x, a.y);
        ((__half2*)&u)[1] = __floats2half2_rn(a.z, a.w);
        ((__half2*)&u)[2] = __floats2half2_rn(b.x, b.y);
        ((__half2*)&u)[3] = __floats2half2_rn(b.z, b.w);
        ((uint4*)dst)[i] = u;
    }
}

__global__ void k_convert(const float* __restrict__ Wout, const float* __restrict__ Wih,
                          const float* __restrict__ Whh)
{
    size_t base = (size_t)blockIdx.x * blockDim.x + threadIdx.x;
    size_t stride = (size_t)gridDim.x * blockDim.x;
    cvt8(Wout, g_Wh, (size_t)Vn * 2048 / 8, base, stride);
    cvt8(Wih, g_Wih_h, (size_t)3 * Hd * Dm / 8, base, stride);
    cvt8(Whh, g_Whh_h, (size_t)3 * Hd * Hd / 8, base, stride);
}

// ------------- K0b: M = emb @ Wq (once per launch) -------------
__global__ void k_prep(const float* __restrict__ emb, const float* __restrict__ Wq)
{
    __shared__ float scol[8][Hd];
    const int hbase = blockIdx.x * 8;
    for (int idx = threadIdx.x; idx < 8 * Hd; idx += 128) {
        int c = idx & 7, a = idx >> 3;
        scol[c][a] = Wq[(size_t)a * Hd + hbase + c];
    }
    __syncthreads();
    const int s = threadIdx.x;
    float acc[8] = {0.f, 0.f, 0.f, 0.f, 0.f, 0.f, 0.f, 0.f};
    const float4* e4 = (const float4*)(emb + (size_t)s * An);
    for (int a4 = 0; a4 < An / 4; a4++) {
        float4 e = e4[a4];
#pragma unroll
        for (int c = 0; c < 8; c++)
            acc[c] += e.x * scol[c][4 * a4] + e.y * scol[c][4 * a4 + 1]
                    + e.z * scol[c][4 * a4 + 2] + e.w * scol[c][4 * a4 + 3];
    }
#pragma unroll
    for (int c = 0; c < 8; c++) g_M[s][hbase + c] = acc[c];
}

// ---- K1: fused small kernel: scalar finalize + GRU + scores + attn ----
__global__ void __launch_bounds__(NTS, 1)
k_small(const float* __restrict__ hidden, const float* __restrict__ emb,
        const float* __restrict__ E, const float* __restrict__ bih,
        const float* __restrict__ bhh, float* __restrict__ out, int step)
{
    const int tid = threadIdx.x, bid = blockIdx.x;
    const int wid = tid >> 5, lane = tid & 31;

    __shared__ float sgi[8][3], sgh[8][3];
    __shared__ float scred[16];

    int word = SOS;
    if (step > 0) {
        unsigned long long best = g_apk[(step - 1) & 1];
        word = (int)(0xFFFFFFFFu - (unsigned)(best & 0xFFFFFFFFull));
        float logZ = logf(g_sum[(step - 1) & 1]);
        if (bid == 0 && tid == 0) {
            g_logZ = logZ;
            out[(size_t)Tn * Vn + (size_t)Tn * Sn + (step - 1)] = (float)word;
        }
        if (step == Tn) {   // tail: finalize last step's log_softmax
            for (int v = bid * NTS + tid; v < Vn; v += NBS * NTS)
                out[(size_t)(step - 1) * Vn + v] -= logZ;
            return;
        }
    }
    if (bid == 0 && tid == 0) { g_apk[step & 1] = 0ull; g_sum[step & 1] = 0.f; }

    const float* h = (step == 0) ? hidden : g_hbuf[(step - 1) & 1];
    float* hn = g_hbuf[step & 1];

    // ===== Phase A: GRU — warp per (unit, gate), fp16 weights ====
    {
        const int ul = wid / 3;        // local unit 0..7
        const int g  = wid % 3;        // gate 0=r 1=z 2=n
        const int u  = bid * 8 + ul;
        const int row = g * Hd + u;
        const float4* x4 = (const float4*)(E + (size_t)word * Dm);
        const float4* h4 = (const float4*)h;
        const uint4* wi = (const uint4*)(g_Wih_h + (size_t)row * Dm);
        const uint4* wh = (const uint4*)(g_Whh_h + (size_t)row * Hd);
        float si = 0.f, sh = 0.f;
#pragma unroll
        for (int j = 0; j < 2; j++) {
            uint4 u8 = wi[lane + 32 * j];
            float4 xa = x4[2 * (lane + 32 * j)];
            float4 xb = x4[2 * (lane + 32 * j) + 1];
            const __half2* hp = (const __half2*)&u8;
            float2 w0 = __half22float2(hp[0]);
            float2 w1 = __half22float2(hp[1]);
            float2 w2 = __half22float2(hp[2]);
            float2 w3 = __half22float2(hp[3]);
            si += w0.x*xa.x + w0.y*xa.y + w1.x*xa.z + w1.y*xa.w
                + w2.x*xb.x + w2.y*xb.y + w3.x*xb.z + w3.y*xb.w;
        }
#pragma unroll
        for (int j = 0; j < 4; j++) {
            uint4 u8 = wh[lane + 32 * j];
            float4 ha = h4[2 * (lane + 32 * j)];
            float4 hb = h4[2 * (lane + 32 * j) + 1];
            const __half2* hp = (const __half2*)&u8;
            float2 w0 = __half22float2(hp[0]);
            float2 w1 = __half22float2(hp[1]);
            float2 w2 = __half22float2(hp[2]);
            float2 w3 = __half22float2(hp[3]);
            sh += w0.x*ha.x + w0.y*ha.y + w1.x*ha.z + w1.y*ha.w
                + w2.x*hb.x + w2.y*hb.y + w3.x*hb.z + w3.y*hb.w;
        }
        si = warp_sum(si); sh = warp_sum(sh);
        if (lane == 0) { sgi[ul][g] = si + bih[row]; sgh[ul][g] = sh + bhh[row]; }
        __syncthreads();
        if (tid < 8) {
            int u2 = bid * 8 + tid;
            float r = 1.f / (1.f + __expf(-(sgi[tid][0] + sgh[tid][0])));
            float z = 1.f / (1.f + __expf(-(sgi[tid][1] + sgh[tid][1])));
            float n = tanhf(sgi[tid][2] + r * sgh[tid][2]);
            hn[u2] = (1.f - z) * n + z * h[u2];
        }
    }
    gsync();

    // ===== Phase C: scores[bid] = M[bid] . hn (512 threads) =====
    if (tid < 512) {
        float2 m2 = ((const float2*)g_M[bid])[tid];
        float2 h2 = ((const float2*)hn)[tid];
        float s = m2.x * h2.x + m2.y * h2.y;
        s = warp_sum(s);
        if (lane == 0) scred[wid] = s;
    }
    __syncthreads();
    if (tid == 0) {
        float s = 0.f;
#pragma unroll
        for (int i = 0; i < 16; i++) s += scred[i];
        g_scores[bid] = s;
    }
    gsync();

    // ===== Phase D: softmax (per-warp redundant) + attn — warp per dim =====
    if (wid < 8) {
        const int d = bid + NBS * wid;   // 0..1023
        float sc0 = g_scores[lane];
        float sc1 = g_scores[lane + 32];
        float sc2 = g_scores[lane + 64];
        float sc3 = g_scores[lane + 96];
        float mx = fmaxf(fmaxf(sc0, sc1), fmaxf(sc2, sc3));
#pragma unroll
        for (int o = 16; o > 0; o >>= 1)
            mx = fmaxf(mx, __shfl_xor_sync(0xffffffffu, mx, o));
        float e0 = __expf(sc0 - mx), e1 = __expf(sc1 - mx);
        float e2 = __expf(sc2 - mx), e3 = __expf(sc3 - mx);
        float ssum = e0 + e1 + e2 + e3;
#pragma unroll
        for (int o = 16; o > 0; o >>= 1)
            ssum += __shfl_xor_sync(0xffffffffu, ssum, o);
        float inv = 1.f / ssum;
        float part = e0 * inv * emb[(size_t)lane * An + d]
                   + e1 * inv * emb[(size_t)(lane + 32) * An + d]
                   + e2 * inv * emb[(size_t)(lane + 64) * An + d]
                   + e3 * inv * emb[(size_t)(lane + 96) * An + d];
        part = warp_sum(part);
        if (lane == 0) g_attn[d] = part;
        if (d == 0) {
            float* wo = out + (size_t)Tn * Vn + (size_t)step * Sn;
            wo[lane]      = e0 * inv;
            wo[lane + 32] = e1 * inv;
            wo[lane + 64] = e2 * inv;
            wo[lane + 96] = e3 * inv;
        }
    }
}

// -- K2: logits GEMV (fp16, 2 rows/warp, 16 rows/block, 256 thr) + atomics --
__global__ void __launch_bounds__(256)
k_logits(const float* __restrict__ bout, float* __restrict__ out, int step)
{
    __shared__ __align__(16) float merge[2 * Hd];
    __shared__ unsigned long long spk[8];
    __shared__ float sse[8];
    const int tid = threadIdx.x, wid = tid >> 5, lane = tid & 31;
    const float* hn = g_hbuf[step & 1];

    if (step > 0 && tid < RPB) {
        int pv = blockIdx.x * RPB + tid;
        if (pv < Vn) out[(size_t)(step - 1) * Vn + pv] -= g_logZ;
    }
    for (int i = tid; i < Hd; i += 256) { merge[i] = hn[i]; merge[Hd + i] = g_attn[i]; }
    __syncthreads();

    const int v0 = blockIdx.x * RPB + wid * 2;
    const int v1 = v0 + 1;
    const bool val0 = (v0 < Vn), val1 = (v1 < Vn);
    float s0 = 0.f, s1 = 0.f;
    {
        const uint4* w4a = (const uint4*)(g_Wh + (size_t)v0 * (2 * Hd));
        const uint4* w4b = (const uint4*)(g_Wh + (size_t)v1 * (2 * Hd));
        const float4* m4 = (const float4*)merge;
#pragma unroll
        for (int j = 0; j < 8; j++) {
            float4 ma = m4[2 * (lane + 32 * j)];
            float4 mb = m4[2 * (lane + 32 * j) + 1];
            if (val0) {
                uint4 u = w4a[lane + 32 * j];
                const __half2* hp = (const __half2*)&u;
                float2 f0 = __half22float2(hp[0]);
                float2 f1 = __half22float2(hp[1]);
                float2 f2 = __half22float2(hp[2]);
                float2 f3 = __half22float2(hp[3]);
                s0 += f0.x*ma.x + f0.y*ma.y + f1.x*ma.z + f1.y*ma.w
                    + f2.x*mb.x + f2.y*mb.y + f3.x*mb.z + f3.y*mb.w;
            }
            if (val1) {
                uint4 u = w4b[lane + 32 * j];
                const __half2* hp = (const __half2*)&u;
                float2 f0 = __half22float2(hp[0]);
                float2 f1 = __half22float2(hp[1]);
                float2 f2 = __half22float2(hp[2]);
                float2 f3 = __half22float2(hp[3]);
                s1 += f0.x*ma.x + f0.y*ma.y + f1.x*ma.z + f1.y*ma.w
                    + f2.x*mb.x + f2.y*mb.y + f3.x*mb.z + f3.y*mb.w;
            }
        }
    }
    s0 = warp_sum(s0);
    s1 = warp_sum(s1);
    if (lane == 0) {
        unsigned long long pk = 0ull;
        float e = 0.f;
        if (val0) {
            float l0 = s0 + bout[v0];
            out[(size_t)step * Vn + v0] = l0;
            unsigned b = __float_as_uint(l0);
            unsigned key = (b & 0x80000000u) ? ~b : (b | 0x80000000u);
            pk = ((unsigned long long)key << 32) |
                 (unsigned long long)(0xFFFFFFFFu - (unsigned)v0);
            e = __expf(l0);
        }
        if (val1) {
            float l1 = s1 + bout[v1];
            out[(size_t)step * Vn + v1] = l1;
            unsigned b = __float_as_uint(l1);
            unsigned key = (b & 0x80000000u) ? ~b : (b | 0x80000000u);
            unsigned long long pk1 = ((unsigned long long)key << 32) |
                                     (unsigned long long)(0xFFFFFFFFu - (unsigned)v1);
            pk = umaxll(pk, pk1);
            e += __expf(l1);
        }
        spk[wid] = pk; sse[wid] = e;
    }
    __syncthreads();
    if (tid == 0) {
        unsigned long long best = spk[0];
        float tot = sse[0];
#pragma unroll
        for (int i = 1; i < 8; i++) { best = umaxll(best, spk[i]); tot += sse[i]; }
        atomicMax(&g_apk[step & 1], best);
        atomicAdd(&g_sum[step & 1], tot);
    }
}

// ---------------- launcher ----------------
extern "C" void kernel_launch(void* const* d_in, const int* in_sizes, int n_in,
                              void* d_out, int out_size)
{
    const float* hidden = (const float*)d_in[0];
    const float* emb    = (const float*)d_in[1];
    const float* E      = (const float*)d_in[2];
    const float* Wih    = (const float*)d_in[3];
    const float* Whh    = (const float*)d_in[4];
    const float* bih    = (const float*)d_in[5];
    const float* bhh    = (const float*)d_in[6];
    const float* Wq     = (const float*)d_in[7];
    const float* Wout   = (const float*)d_in[8];
    const float* bout   = (const float*)d_in[9];
    float* out = (float*)d_out;

    k_convert<<<2048, 256>>>(Wout, Wih, Whh);
    k_prep<<<Sn, 128>>>(emb, Wq);
    for (int t = 0; t < Tn; t++) {
        k_small <<<NBS, NTS>>>(hidden, emb, E, bih, bhh, out, t);
        k_logits<<<NB3, 256>>>(bout, out, t);
    }
    k_small<<<NBS, NTS>>>(hidden, emb, E, bih, bhh, out, Tn);
}